// round 11
// baseline (speedup 1.0000x reference)
#include <cuda_runtime.h>

// HierarchicalPDFSampler — hybrid fill/uniform version.
// 1 warp per ray.
// Phase A (divergent, tiny body): fill a per-ray byte table tab[j] = owning
//   segment index; publish per-segment (slope, off, split) pack to smem.
// Phase B (uniform): each lane computes exactly 4 samples via 1 table LDS
//   + 1 pack LDS.128 per sample; closed-form merge position.
// Depth merge positions closed-form from split indices (no sort, no atomics).

constexpr int NC   = 64;
constexpr int NOUT = 192;
constexpr int WPB  = 8;
constexpr float INV127 = 1.0f / 127.0f;

// ~smallest j in [0,128] with j*INV127 >= c (uncorrected; tiling repaired later)
__device__ __forceinline__ int start_guess(float c) {
    int g = (int)ceilf(c * 127.0f);
    return max(0, min(g, 128));
}

// ~first j in [jS, jE] with fmaf(j*INV127, slope, offv) >= dn (uncorrected;
// any value in [jS,jE] yields a valid permutation — used consistently by both
// sample and depth placement)
__device__ __forceinline__ int split_guess(float slope, float offv, float dn,
                                           int jS, int jE) {
    const float uth = __fdividef(dn - offv, slope);   // inf/nan ok -> clamped
    int g = (int)ceilf(uth * 127.0f);
    return max(jS, min(g, jE));
}

__global__ __launch_bounds__(WPB * 32)
void hier_pdf_kernel(const float* __restrict__ depth,
                     const float* __restrict__ weights,
                     float* __restrict__ out,
                     int nrays)
{
    __shared__ float         s_merg_all[WPB * NOUT];
    __shared__ float4        s_pack_all[WPB * 64];
    __shared__ unsigned char s_tab_all [WPB * 128];

    const int lane = threadIdx.x & 31;
    const int warp = threadIdx.x >> 5;
    const int ray  = blockIdx.x * WPB + warp;
    if (ray >= nrays) return;

    float*         s_merg = s_merg_all + warp * NOUT;
    float4*        s_pack = s_pack_all + warp * 64;
    unsigned char* s_tab  = s_tab_all  + warp * 128;

    // ---- coalesced float2 loads ----
    const float2 d2 = ((const float2*)(depth   + (size_t)ray * NC))[lane];
    const float2 w2 = ((const float2*)(weights + (size_t)ray * NC))[lane];

    // ---- bin midpoints ----
    const float dnext  = __shfl_down_sync(0xffffffffu, d2.x, 1);  // depth[2l+2]
    const float b_even = 0.5f * (d2.x + d2.y);                    // bins[2l]
    const float b_odd  = 0.5f * (d2.y + dnext);                   // bins[2l+1]

    // ---- cdf via warp pair-scan of weights[1..62]+1e-5 ----
    const float a0 = (lane == 0)  ? 0.0f : (w2.x + 1e-5f);
    const float a1 = (lane == 31) ? 0.0f : (w2.y + 1e-5f);
    float incl = a0 + a1;
    #pragma unroll
    for (int off = 1; off < 32; off <<= 1) {
        const float t = __shfl_up_sync(0xffffffffu, incl, off);
        if (lane >= off) incl += t;
    }
    const float S      = __shfl_sync(0xffffffffu, incl, 31);
    const float invS   = __fdividef(1.0f, S);
    const float p_odd  = incl * invS;          // cdf[2l+1]
    const float p_even = (incl - a1) * invS;   // cdf[2l] (lane0: exactly 0)

    // ---- segment start indices + tiling repair (prefix-max) ----
    int jA = start_guess(p_even);   // start of segment b=2l
    int jB = start_guess(p_odd);    // start of segment b=2l+1
    jB = max(jB, jA);
    int v = jB;
    #pragma unroll
    for (int off = 1; off < 32; off <<= 1) {
        const int t = __shfl_up_sync(0xffffffffu, v, off);
        if (lane >= off) v = max(v, t);
    }
    int pm = __shfl_up_sync(0xffffffffu, v, 1);
    if (lane == 0) pm = 0;
    jA = max(jA, pm);
    jB = max(jB, jA);
    int jC = __shfl_down_sync(0xffffffffu, jA, 1);
    if (lane == 31) jC = 128;

    const float p_next = __shfl_down_sync(0xffffffffu, p_even, 1);  // cdf[2l+2]
    const float b_next = __shfl_down_sync(0xffffffffu, b_even, 1);  // bins[2l+2]

    // ---- segment coefficients ----
    // seg b=2l (lane31: b=62, 'above' clamps -> slope 0, range to 128)
    float ca1, ba1; int jE1;
    if (lane == 31) { ca1 = p_even; ba1 = b_even; jE1 = 128; }
    else            { ca1 = p_odd;  ba1 = b_odd;  jE1 = jB;  }
    const float den1 = ca1 - p_even;
    const float inv1 = (den1 < 1e-5f) ? 1.0f : __fdividef(1.0f, den1);
    const float slope1 = (ba1 - b_even) * inv1;
    const float off1   = fmaf(-p_even, slope1, b_even);
    const int   sp1    = split_guess(slope1, off1, d2.y, jA, jE1);

    // seg b=2l+1 (lanes 0..30); lane31: sp2 = 128
    float slope2 = 0.0f, off2 = 0.0f;
    int sp2 = jC;
    if (lane < 31) {
        const float den2 = p_next - p_odd;
        const float inv2 = (den2 < 1e-5f) ? 1.0f : __fdividef(1.0f, den2);
        slope2 = (b_next - b_odd) * inv2;
        off2   = fmaf(-p_odd, slope2, b_odd);
        sp2    = split_guess(slope2, off2, dnext, jB, jC);
    }

    // ---- publish per-segment pack (slope, off, split) ----
    const int b1 = 2 * lane, b2 = 2 * lane + 1;
    s_pack[b1] = make_float4(slope1, off1, __int_as_float(sp1), 0.0f);
    if (lane < 31)
        s_pack[b2] = make_float4(slope2, off2, __int_as_float(sp2), 0.0f);

    // ---- depth positions: e_i = jSplit(i-1), e_0 = 0 ----
    int e0 = __shfl_up_sync(0xffffffffu, sp2, 1);      // jSplit(2l-1)
    if (lane == 0) e0 = 0;
    s_merg[b1 + e0]      = d2.x;
    s_merg[b2 + sp1]     = d2.y;

    // ---- Phase A: divergent owner-table fill (tiny body) ----
    const int jEnd  = (lane == 31) ? 128 : jC;
    const int jBeff = (lane == 31) ? 128 : jB;
    #pragma unroll 1
    for (int j = jA; j < jEnd; ++j)
        s_tab[j] = (unsigned char)((j >= jBeff) ? b2 : b1);
    __syncwarp();

    // ---- Phase B: uniform sample computation, 4 per lane ----
    const unsigned tw = *(const unsigned*)(s_tab + 4 * lane);
    #pragma unroll
    for (int k = 0; k < 4; ++k) {
        const int j = 4 * lane + k;
        const int b = (tw >> (8 * k)) & 0xff;
        const float4 c = s_pack[b];
        const float  u = (float)j * INV127;            // matches split predicate
        const float  s = fmaf(u, c.x, c.y);
        const int   sp = __float_as_int(c.z);
        const int  pos = j + b + 1 + (j >= sp ? 1 : 0);
        s_merg[pos] = s;
    }
    __syncwarp();

    // ---- coalesced float4 store: 48 float4 per ray ----
    float4* orow = (float4*)(out + (size_t)ray * NOUT);
    const float4* m4 = (const float4*)s_merg;
    orow[lane] = m4[lane];
    if (lane < 16) orow[32 + lane] = m4[32 + lane];
}

extern "C" void kernel_launch(void* const* d_in, const int* in_sizes, int n_in,
                              void* d_out, int out_size)
{
    const float* depth   = (const float*)d_in[0];  // depth_rays_values_coarse [R,64]
    const float* weights = (const float*)d_in[1];  // coarse_weights           [R,64]
    float* out = (float*)d_out;                    // [R,192]

    const int nrays  = in_sizes[0] / NC;
    const int blocks = (nrays + WPB - 1) / WPB;
    hier_pdf_kernel<<<blocks, WPB * 32>>>(depth, weights, out, nrays);
}

// round 12
// speedup vs baseline: 1.1739x; 1.1739x over previous
#include <cuda_runtime.h>

// HierarchicalPDFSampler — R10 structure + verified-safe instruction cuts.
// 1 warp per ray.
//  - inverse-CDF by per-segment direct index ranges (u is linspace)
//  - start indices: bare ceil-guess (tiling validity enforced by prefix-max)
//  - split indices: fast-div guess, clamped, UNcorrected (R11-verified safe)
//  - fused slope division (ba-bb)/den via __fdividef
//  - unified position formula pos = j + base + (j>=sp1) + (j>=sp2)
//  - incremental u in the sample loop
//  - closed-form merge ranks (no sort, no atomics, no tables)

constexpr int NC   = 64;
constexpr int NOUT = 192;
constexpr int WPB  = 8;
constexpr float INV127 = 1.0f / 127.0f;

// ~smallest j in [0,128] with j*INV127 >= c (uncorrected; repaired by prefix-max)
__device__ __forceinline__ int start_guess(float c) {
    int g = (int)ceilf(c * 127.0f);
    return max(0, min(g, 128));
}

// ~first j in [jS, jE] with fmaf(j*INV127, slope, offv) >= dn (clamped guess;
// any value in [jS,jE] yields a valid permutation — consumed consistently by
// both sample and depth placement)
__device__ __forceinline__ int split_guess(float slope, float offv, float dn,
                                           int jS, int jE) {
    const float uth = __fdividef(dn - offv, slope);   // inf/nan ok -> clamped
    int g = (int)ceilf(uth * 127.0f);
    return max(jS, min(g, jE));
}

__global__ __launch_bounds__(WPB * 32)
void hier_pdf_kernel(const float* __restrict__ depth,
                     const float* __restrict__ weights,
                     float* __restrict__ out,
                     int nrays)
{
    __shared__ float s_merg_all[WPB * NOUT];

    const int lane = threadIdx.x & 31;
    const int warp = threadIdx.x >> 5;
    const int ray  = blockIdx.x * WPB + warp;
    if (ray >= nrays) return;

    float* s_merg = s_merg_all + warp * NOUT;

    // ---- coalesced float2 loads ----
    const float2 d2 = ((const float2*)(depth   + (size_t)ray * NC))[lane];
    const float2 w2 = ((const float2*)(weights + (size_t)ray * NC))[lane];

    // ---- bin midpoints ----
    const float dnext  = __shfl_down_sync(0xffffffffu, d2.x, 1);  // depth[2l+2]
    const float b_even = 0.5f * (d2.x + d2.y);                    // bins[2l]
    const float b_odd  = 0.5f * (d2.y + dnext);                   // bins[2l+1]

    // ---- cdf via warp pair-scan of weights[1..62]+1e-5 ----
    const float a0 = (lane == 0)  ? 0.0f : (w2.x + 1e-5f);
    const float a1 = (lane == 31) ? 0.0f : (w2.y + 1e-5f);
    float incl = a0 + a1;
    #pragma unroll
    for (int off = 1; off < 32; off <<= 1) {
        const float t = __shfl_up_sync(0xffffffffu, incl, off);
        if (lane >= off) incl += t;
    }
    const float S      = __shfl_sync(0xffffffffu, incl, 31);
    const float invS   = __fdividef(1.0f, S);
    const float p_odd  = incl * invS;          // cdf[2l+1]
    const float p_even = (incl - a1) * invS;   // cdf[2l] (lane0: exactly 0)

    // ---- segment start indices + tiling repair (prefix-max) ----
    int jA = start_guess(p_even);   // start of segment b=2l
    int jB = start_guess(p_odd);    // start of segment b=2l+1
    jB = max(jB, jA);
    int v = jB;
    #pragma unroll
    for (int off = 1; off < 32; off <<= 1) {
        const int t = __shfl_up_sync(0xffffffffu, v, off);
        if (lane >= off) v = max(v, t);
    }
    int pm = __shfl_up_sync(0xffffffffu, v, 1);
    if (lane == 0) pm = 0;
    jA = max(jA, pm);
    jB = max(jB, jA);
    int jC = __shfl_down_sync(0xffffffffu, jA, 1);
    if (lane == 31) jC = 128;

    const float p_next = __shfl_down_sync(0xffffffffu, p_even, 1);  // cdf[2l+2]
    const float b_next = __shfl_down_sync(0xffffffffu, b_even, 1);  // bins[2l+2]

    // ---- segment coefficients ----
    // seg b=2l (lane31: b=62, 'above' clamps -> slope 0, range to 128)
    float ca1, ba1; int jE1;
    if (lane == 31) { ca1 = p_even; ba1 = b_even; jE1 = 128; }
    else            { ca1 = p_odd;  ba1 = b_odd;  jE1 = jB;  }
    const float den1   = ca1 - p_even;
    const float num1   = ba1 - b_even;
    const float slope1 = (den1 < 1e-5f) ? num1 : __fdividef(num1, den1);
    const float off1   = fmaf(-p_even, slope1, b_even);
    const int   sp1    = split_guess(slope1, off1, d2.y, jA, jE1);

    // seg b=2l+1 (lanes 0..30); lane31: sp2 = 128 (never triggers)
    float slope2 = 0.0f, off2 = 0.0f;
    int sp2 = jC;
    if (lane < 31) {
        const float den2 = p_next - p_odd;
        const float num2 = b_next - b_odd;
        slope2 = (den2 < 1e-5f) ? num2 : __fdividef(num2, den2);
        off2   = fmaf(-p_odd, slope2, b_odd);
        sp2    = split_guess(slope2, off2, dnext, jB, jC);
    }

    // ---- depth positions: e_i = jSplit(i-1), e_0 = 0 ----
    int e0 = __shfl_up_sync(0xffffffffu, sp2, 1);      // jSplit(2l-1)
    if (lane == 0) e0 = 0;
    s_merg[2 * lane     + e0]  = d2.x;
    s_merg[2 * lane + 1 + sp1] = d2.y;

    // ---- unified sample loop over both owned segments ----
    // pos = j + base + (j>=sp1) + (j>=sp2): sp1 <= jB (clamped) so the
    // second segment sees +1 from sp1; sp2 >= jB so the first sees 0.
    const int jEnd  = (lane == 31) ? 128 : jC;
    const int jBeff = (lane == 31) ? 128 : jB;
    const int base  = 2 * lane + 1;
    float u = (float)jA * INV127;
    #pragma unroll 1
    for (int j = jA; j < jEnd; ++j) {
        const bool second = (j >= jBeff);
        const float sl = second ? slope2 : slope1;
        const float of = second ? off2   : off1;
        const float s  = fmaf(u, sl, of);
        int pos = j + base;
        pos += (j >= sp1) ? 1 : 0;
        pos += (j >= sp2) ? 1 : 0;
        s_merg[pos] = s;
        u += INV127;
    }
    __syncwarp();

    // ---- coalesced float4 store: 48 float4 per ray ----
    float4* orow = (float4*)(out + (size_t)ray * NOUT);
    const float4* m4 = (const float4*)s_merg;
    orow[lane] = m4[lane];
    if (lane < 16) orow[32 + lane] = m4[32 + lane];
}

extern "C" void kernel_launch(void* const* d_in, const int* in_sizes, int n_in,
                              void* d_out, int out_size)
{
    const float* depth   = (const float*)d_in[0];  // depth_rays_values_coarse [R,64]
    const float* weights = (const float*)d_in[1];  // coarse_weights           [R,64]
    float* out = (float*)d_out;                    // [R,192]

    const int nrays  = in_sizes[0] / NC;
    const int blocks = (nrays + WPB - 1) / WPB;
    hier_pdf_kernel<<<blocks, WPB * 32>>>(depth, weights, out, nrays);
}

// round 13
// speedup vs baseline: 1.2544x; 1.0686x over previous
#include <cuda_runtime.h>

// HierarchicalPDFSampler — R12 structure, sample loop split into two tight
// sequential per-segment loops (no per-iter coefficient selects).
// 1 warp per ray.
//  - inverse-CDF by per-segment direct index ranges (u is linspace)
//  - start indices: bare ceil-guess (tiling validity enforced by prefix-max)
//  - split indices: fast-div guess, clamped, uncorrected (R11-verified safe)
//  - loop1: seg b=2l over [jA, jBeff), pos = j+base+(j>=sp1)
//  - loop2: seg b=2l+1 over [jBeff, jEnd), pos = j+base+1+(j>=sp2)
//  - closed-form merge ranks (no sort, no atomics, no tables)

constexpr int NC   = 64;
constexpr int NOUT = 192;
constexpr int WPB  = 8;
constexpr float INV127 = 1.0f / 127.0f;

// ~smallest j in [0,128] with j*INV127 >= c (uncorrected; repaired by prefix-max)
__device__ __forceinline__ int start_guess(float c) {
    int g = (int)ceilf(c * 127.0f);
    return max(0, min(g, 128));
}

// ~first j in [jS, jE] with fmaf(j*INV127, slope, offv) >= dn (clamped guess;
// any value in [jS,jE] yields a valid permutation — consumed consistently by
// both sample and depth placement)
__device__ __forceinline__ int split_guess(float slope, float offv, float dn,
                                           int jS, int jE) {
    const float uth = __fdividef(dn - offv, slope);   // inf/nan ok -> clamped
    int g = (int)ceilf(uth * 127.0f);
    return max(jS, min(g, jE));
}

__global__ __launch_bounds__(WPB * 32)
void hier_pdf_kernel(const float* __restrict__ depth,
                     const float* __restrict__ weights,
                     float* __restrict__ out,
                     int nrays)
{
    __shared__ float s_merg_all[WPB * NOUT];

    const int lane = threadIdx.x & 31;
    const int warp = threadIdx.x >> 5;
    const int ray  = blockIdx.x * WPB + warp;
    if (ray >= nrays) return;

    float* s_merg = s_merg_all + warp * NOUT;

    // ---- coalesced float2 loads ----
    const float2 d2 = ((const float2*)(depth   + (size_t)ray * NC))[lane];
    const float2 w2 = ((const float2*)(weights + (size_t)ray * NC))[lane];

    // ---- bin midpoints ----
    const float dnext  = __shfl_down_sync(0xffffffffu, d2.x, 1);  // depth[2l+2]
    const float b_even = 0.5f * (d2.x + d2.y);                    // bins[2l]
    const float b_odd  = 0.5f * (d2.y + dnext);                   // bins[2l+1]

    // ---- cdf via warp pair-scan of weights[1..62]+1e-5 ----
    const float a0 = (lane == 0)  ? 0.0f : (w2.x + 1e-5f);
    const float a1 = (lane == 31) ? 0.0f : (w2.y + 1e-5f);
    float incl = a0 + a1;
    #pragma unroll
    for (int off = 1; off < 32; off <<= 1) {
        const float t = __shfl_up_sync(0xffffffffu, incl, off);
        if (lane >= off) incl += t;
    }
    const float S      = __shfl_sync(0xffffffffu, incl, 31);
    const float invS   = __fdividef(1.0f, S);
    const float p_odd  = incl * invS;          // cdf[2l+1]
    const float p_even = (incl - a1) * invS;   // cdf[2l] (lane0: exactly 0)

    // ---- segment start indices + tiling repair (prefix-max) ----
    int jA = start_guess(p_even);   // start of segment b=2l
    int jB = start_guess(p_odd);    // start of segment b=2l+1
    jB = max(jB, jA);
    int v = jB;
    #pragma unroll
    for (int off = 1; off < 32; off <<= 1) {
        const int t = __shfl_up_sync(0xffffffffu, v, off);
        if (lane >= off) v = max(v, t);
    }
    int pm = __shfl_up_sync(0xffffffffu, v, 1);
    if (lane == 0) pm = 0;
    jA = max(jA, pm);
    jB = max(jB, jA);
    int jC = __shfl_down_sync(0xffffffffu, jA, 1);
    if (lane == 31) jC = 128;

    const float p_next = __shfl_down_sync(0xffffffffu, p_even, 1);  // cdf[2l+2]
    const float b_next = __shfl_down_sync(0xffffffffu, b_even, 1);  // bins[2l+2]

    // ---- segment coefficients ----
    // seg b=2l (lane31: b=62, 'above' clamps -> slope 0, range to 128)
    float ca1, ba1; int jE1;
    if (lane == 31) { ca1 = p_even; ba1 = b_even; jE1 = 128; }
    else            { ca1 = p_odd;  ba1 = b_odd;  jE1 = jB;  }
    const float den1   = ca1 - p_even;
    const float num1   = ba1 - b_even;
    const float slope1 = (den1 < 1e-5f) ? num1 : __fdividef(num1, den1);
    const float off1   = fmaf(-p_even, slope1, b_even);
    const int   sp1    = split_guess(slope1, off1, d2.y, jA, jE1);

    // seg b=2l+1 (lanes 0..30); lane31: sp2 = 128 (never triggers)
    float slope2 = 0.0f, off2 = 0.0f;
    int sp2 = jC;
    if (lane < 31) {
        const float den2 = p_next - p_odd;
        const float num2 = b_next - b_odd;
        slope2 = (den2 < 1e-5f) ? num2 : __fdividef(num2, den2);
        off2   = fmaf(-p_odd, slope2, b_odd);
        sp2    = split_guess(slope2, off2, dnext, jB, jC);
    }

    // ---- depth positions: e_i = jSplit(i-1), e_0 = 0 ----
    int e0 = __shfl_up_sync(0xffffffffu, sp2, 1);      // jSplit(2l-1)
    if (lane == 0) e0 = 0;
    s_merg[2 * lane     + e0]  = d2.x;
    s_merg[2 * lane + 1 + sp1] = d2.y;

    // ---- sample loops: seg1 then seg2, fixed coefficients each ----
    const int jEnd  = (lane == 31) ? 128 : jC;
    const int jBeff = (lane == 31) ? 128 : jB;   // lane31: loop2 gets 0 trips
    const int base  = 2 * lane + 1;
    float u = (float)jA * INV127;

    int j = jA;
    #pragma unroll 1
    for (; j < jBeff; ++j) {                     // segment b=2l
        const float s = fmaf(u, slope1, off1);
        const int pos = j + base + (j >= sp1 ? 1 : 0);
        s_merg[pos] = s;
        u += INV127;
    }
    #pragma unroll 1
    for (; j < jEnd; ++j) {                      // segment b=2l+1
        const float s = fmaf(u, slope2, off2);
        const int pos = j + base + 1 + (j >= sp2 ? 1 : 0);
        s_merg[pos] = s;
        u += INV127;
    }
    __syncwarp();

    // ---- coalesced float4 store: 48 float4 per ray ----
    float4* orow = (float4*)(out + (size_t)ray * NOUT);
    const float4* m4 = (const float4*)s_merg;
    orow[lane] = m4[lane];
    if (lane < 16) orow[32 + lane] = m4[32 + lane];
}

extern "C" void kernel_launch(void* const* d_in, const int* in_sizes, int n_in,
                              void* d_out, int out_size)
{
    const float* depth   = (const float*)d_in[0];  // depth_rays_values_coarse [R,64]
    const float* weights = (const float*)d_in[1];  // coarse_weights           [R,64]
    float* out = (float*)d_out;                    // [R,192]

    const int nrays  = in_sizes[0] / NC;
    const int blocks = (nrays + WPB - 1) / WPB;
    hier_pdf_kernel<<<blocks, WPB * 32>>>(depth, weights, out, nrays);
}